// round 3
// baseline (speedup 1.0000x reference)
#include <cuda_runtime.h>

#define N_NODES 100000
#define N_EDGES 1600000
#define HID 64
#define SCAN_T 512
#define SCAN_NB ((N_NODES + SCAN_T - 1) / SCAN_T)   // 196
#define MPAD 132   // sA row stride (multiple of 4 for float4-on-k; 4m+2i bank pattern = 2-way max)

// ---------------- scratch (device globals; no runtime allocation) ----------------
__device__ float g_hA[N_NODES * HID];
__device__ float g_hB[N_NODES * HID];
__device__ int   g_csr[N_EDGES];
__device__ int   g_cnt[N_NODES];
__device__ int   g_off[N_NODES + 1];
__device__ int   g_wp[N_NODES];
__device__ int   g_bsum[SCAN_NB + 1];
__device__ int   g_is64;

// ---------------- edge dtype detection ----------------
// int64 little-endian: high 32-bit word of every entry is 0 (values in [0,100000)).
// int32: odd words are real indices -> essentially never all zero over 64 samples.
__global__ void k_detect(const int* __restrict__ e32) {
    if (threadIdx.x == 0) {
        int is64 = 1;
        for (int i = 0; i < 64; i++)
            if (e32[2 * i + 1] != 0) { is64 = 0; break; }
        g_is64 = is64;
    }
}

__device__ __forceinline__ int edge_at(const void* eptr, long long idx, int is64) {
    if (is64) return (int)((const long long*)eptr)[idx];
    return ((const int*)eptr)[idx];
}

// ---------------- CSR build ----------------
__global__ void k_zero_cnt() {
    int i = blockIdx.x * blockDim.x + threadIdx.x;
    if (i < N_NODES) g_cnt[i] = 0;
}

__global__ void k_hist(const void* __restrict__ eptr) {
    long long e = (long long)blockIdx.x * blockDim.x + threadIdx.x;
    if (e >= N_EDGES) return;
    int d = edge_at(eptr, (long long)N_EDGES + e, g_is64);
    atomicAdd(&g_cnt[d], 1);
}

__global__ void k_scan1() {
    __shared__ int s[SCAN_T];
    int t = threadIdx.x;
    int i = blockIdx.x * SCAN_T + t;
    int v = (i < N_NODES) ? g_cnt[i] : 0;
    s[t] = v;
    __syncthreads();
    for (int o = 1; o < SCAN_T; o <<= 1) {
        int add = (t >= o) ? s[t - o] : 0;
        __syncthreads();
        s[t] += add;
        __syncthreads();
    }
    if (i < N_NODES) g_off[i] = s[t] - v;
    if (t == SCAN_T - 1) g_bsum[blockIdx.x] = s[t];
}

__global__ void k_scan2(int nblk) {
    if (threadIdx.x == 0) {
        int acc = 0;
        for (int b = 0; b < nblk; b++) {
            int t = g_bsum[b];
            g_bsum[b] = acc;
            acc += t;
        }
        g_off[N_NODES] = acc;
    }
}

__global__ void k_scan3() {
    int i = blockIdx.x * SCAN_T + threadIdx.x;
    if (i < N_NODES) {
        int v = g_off[i] + g_bsum[blockIdx.x];
        g_off[i] = v;
        g_wp[i] = v;
    }
}

__global__ void k_scatter(const void* __restrict__ eptr) {
    long long e = (long long)blockIdx.x * blockDim.x + threadIdx.x;
    if (e >= N_EDGES) return;
    int is64 = g_is64;
    int s = edge_at(eptr, e, is64);
    int d = edge_at(eptr, (long long)N_EDGES + e, is64);
    int pos = atomicAdd(&g_wp[d], 1);
    g_csr[pos] = s;
}

// ---------------- pre-MLP ----------------
__global__ void k_pre(const float* __restrict__ x, const float* __restrict__ W,
                      const float* __restrict__ b, float* __restrict__ h) {
    int idx = blockIdx.x * blockDim.x + threadIdx.x;
    if (idx >= N_NODES * HID) return;
    int i = idx >> 6, j = idx & 63;
    float acc = b[j]
              + x[i * 3 + 0] * W[j * 3 + 0]
              + x[i * 3 + 1] * W[j * 3 + 1]
              + x[i * 3 + 2] * W[j * 3 + 2];
    h[idx] = fmaxf(acc, 0.0f);
}

// ---------------- fused layer: agg (CSR gather -> smem) + dual GEMM (+ optional post) --------
// smem: sW [128][64] (k-major, 32KB) + sA [128][MPAD] (m-major, 67.6KB) = 100352 B
#define LAYER_SMEM ((128 * HID + 128 * MPAD) * 4)

template <int LAST>
__global__ void __launch_bounds__(256, 2) k_layer(
        const float* __restrict__ hin,
        const float* __restrict__ relW, const float* __restrict__ relb,
        const float* __restrict__ rootW,
        const float* __restrict__ postW, const float* __restrict__ postb,
        float* __restrict__ hout) {
    extern __shared__ float smem[];
    float* sW = smem;                 // [k=0..127][j=0..63]
    float* sA = smem + 128 * HID;     // [m=0..127][k padded to MPAD]
    const int tid = threadIdx.x;
    const int n0 = blockIdx.x * 128;

    // --- load combined weights (k-major): k<64 -> relW, k>=64 -> rootW ---
    for (int f = tid; f < 128 * HID; f += 256) {
        int k = f >> 6, j = f & 63;
        sW[f] = (k < 64) ? relW[j * HID + k] : rootW[j * HID + (k - 64)];
    }

    // --- aggregation phase: warp per node stream, lane owns 2 columns (float2) ---
    {
        const int warp = tid >> 5, lane = tid & 31;
        const float2* __restrict__ h2 = (const float2*)hin;
#pragma unroll 1
        for (int i = 0; i < 16; i++) {
            int m = warp * 16 + i;
            int n = n0 + m;
            float2 acc = make_float2(0.f, 0.f);
            float2 root = make_float2(0.f, 0.f);
            if (n < N_NODES) {
                root = __ldg(&h2[n * 32 + lane]);
                int s = g_off[n], e = g_off[n + 1];
                int k = s;
                // unrolled by 8 for memory-level parallelism
                for (; k + 8 <= e; k += 8) {
                    int s0 = g_csr[k + 0], s1 = g_csr[k + 1], s2 = g_csr[k + 2], s3 = g_csr[k + 3];
                    int s4 = g_csr[k + 4], s5 = g_csr[k + 5], s6 = g_csr[k + 6], s7 = g_csr[k + 7];
                    float2 v0 = __ldg(&h2[s0 * 32 + lane]);
                    float2 v1 = __ldg(&h2[s1 * 32 + lane]);
                    float2 v2 = __ldg(&h2[s2 * 32 + lane]);
                    float2 v3 = __ldg(&h2[s3 * 32 + lane]);
                    float2 v4 = __ldg(&h2[s4 * 32 + lane]);
                    float2 v5 = __ldg(&h2[s5 * 32 + lane]);
                    float2 v6 = __ldg(&h2[s6 * 32 + lane]);
                    float2 v7 = __ldg(&h2[s7 * 32 + lane]);
                    acc.x += ((v0.x + v1.x) + (v2.x + v3.x)) + ((v4.x + v5.x) + (v6.x + v7.x));
                    acc.y += ((v0.y + v1.y) + (v2.y + v3.y)) + ((v4.y + v5.y) + (v6.y + v7.y));
                }
                for (; k < e; k++) {
                    int src = g_csr[k];
                    float2 v = __ldg(&h2[src * 32 + lane]);
                    acc.x += v.x; acc.y += v.y;
                }
            }
            float* row = &sA[m * MPAD];
            row[2 * lane]      = acc.x;
            row[2 * lane + 1]  = acc.y;
            row[64 + 2 * lane] = root.x;
            row[65 + 2 * lane] = root.y;
        }
    }
    __syncthreads();

    // --- GEMM phase: thread (r,c): rows r*8..r*8+7, cols 4c..4c+3 ---
    const int r = tid >> 4;
    const int c = tid & 15;
    float acc[8][4];
#pragma unroll
    for (int i = 0; i < 8; i++)
#pragma unroll
        for (int j = 0; j < 4; j++) acc[i][j] = 0.f;

    const float4* sWv = (const float4*)sW;
#pragma unroll 1
    for (int k4 = 0; k4 < 128; k4 += 4) {
        float4 a[8];
#pragma unroll
        for (int i = 0; i < 8; i++)
            a[i] = *(const float4*)&sA[(r * 8 + i) * MPAD + k4];
#pragma unroll
        for (int kk = 0; kk < 4; kk++) {
            float4 w = sWv[(k4 + kk) * 16 + c];
#pragma unroll
            for (int i = 0; i < 8; i++) {
                float av = (kk == 0) ? a[i].x : (kk == 1) ? a[i].y : (kk == 2) ? a[i].z : a[i].w;
                acc[i][0] += av * w.x;
                acc[i][1] += av * w.y;
                acc[i][2] += av * w.z;
                acc[i][3] += av * w.w;
            }
        }
    }

    float4 bb = *(const float4*)&relb[c * 4];

    if (!LAST) {
#pragma unroll
        for (int i = 0; i < 8; i++) {
            int n = n0 + r * 8 + i;
            if (n < N_NODES) {
                float4 o;
                o.x = fmaxf(acc[i][0] + bb.x, 0.f);
                o.y = fmaxf(acc[i][1] + bb.y, 0.f);
                o.z = fmaxf(acc[i][2] + bb.z, 0.f);
                o.w = fmaxf(acc[i][3] + bb.w, 0.f);
                *(float4*)&hout[n * HID + c * 4] = o;
            }
        }
    } else {
        // stage relu(h3) into sA, then fused post-MLP: out = relu(h3 @ postW.T + postb)
        __syncthreads();   // everyone done reading sA
#pragma unroll
        for (int i = 0; i < 8; i++) {
            float* row = &sA[(r * 8 + i) * MPAD + c * 4];
            row[0] = fmaxf(acc[i][0] + bb.x, 0.f);
            row[1] = fmaxf(acc[i][1] + bb.y, 0.f);
            row[2] = fmaxf(acc[i][2] + bb.z, 0.f);
            row[3] = fmaxf(acc[i][3] + bb.w, 0.f);
        }
        __syncthreads();
        if (tid < 128) {
            int n = n0 + tid;
            if (n < N_NODES) {
                float a0 = postb[0], a1 = postb[1];
                const float* row = &sA[tid * MPAD];
#pragma unroll 8
                for (int j = 0; j < 64; j++) {
                    float v = row[j];
                    a0 += v * __ldg(&postW[j]);
                    a1 += v * __ldg(&postW[64 + j]);
                }
                hout[2 * n + 0] = fmaxf(a0, 0.f);
                hout[2 * n + 1] = fmaxf(a1, 0.f);
            }
        }
    }
}

// ---------------- launch ----------------
extern "C" void kernel_launch(void* const* d_in, const int* in_sizes, int n_in,
                              void* d_out, int out_size) {
    const float* x     = (const float*)d_in[0];
    const void*  ei    = d_in[1];
    const float* preW  = (const float*)d_in[2];
    const float* preb  = (const float*)d_in[3];
    const float* postW = (const float*)d_in[4];
    const float* postb = (const float*)d_in[5];
    const float* relW[3]  = {(const float*)d_in[6],  (const float*)d_in[9],  (const float*)d_in[12]};
    const float* relb[3]  = {(const float*)d_in[7],  (const float*)d_in[10], (const float*)d_in[13]};
    const float* rootW[3] = {(const float*)d_in[8],  (const float*)d_in[11], (const float*)d_in[14]};
    float* out = (float*)d_out;

    cudaFuncSetAttribute(k_layer<0>, cudaFuncAttributeMaxDynamicSharedMemorySize, LAYER_SMEM);
    cudaFuncSetAttribute(k_layer<1>, cudaFuncAttributeMaxDynamicSharedMemorySize, LAYER_SMEM);

    float *hA, *hB;
    cudaGetSymbolAddress((void**)&hA, g_hA);
    cudaGetSymbolAddress((void**)&hB, g_hB);

    // CSR build
    k_detect<<<1, 32>>>((const int*)ei);
    k_zero_cnt<<<(N_NODES + 255) / 256, 256>>>();
    k_hist<<<(N_EDGES + 255) / 256, 256>>>(ei);
    k_scan1<<<SCAN_NB, SCAN_T>>>();
    k_scan2<<<1, 32>>>(SCAN_NB);
    k_scan3<<<SCAN_NB, SCAN_T>>>();
    k_scatter<<<(N_EDGES + 255) / 256, 256>>>(ei);

    // pre-MLP
    k_pre<<<(N_NODES * HID + 255) / 256, 256>>>(x, preW, preb, hA);

    const int blocks = (N_NODES + 127) / 128;
    // layer 0: hA -> hB ; layer 1: hB -> hA ; layer 2 (last): hA -> out
    k_layer<0><<<blocks, 256, LAYER_SMEM>>>(hA, relW[0], relb[0], rootW[0], postW, postb, hB);
    k_layer<0><<<blocks, 256, LAYER_SMEM>>>(hB, relW[1], relb[1], rootW[1], postW, postb, hA);
    k_layer<1><<<blocks, 256, LAYER_SMEM>>>(hA, relW[2], relb[2], rootW[2], postW, postb, out);
}

// round 5
// speedup vs baseline: 1.5784x; 1.5784x over previous
#include <cuda_runtime.h>
#include <cstdint>

#define N_NODES 100000
#define N_EDGES 1600000
#define HID 64
#define SCAN_T 512
#define SCAN_NB ((N_NODES + SCAN_T - 1) / SCAN_T)   // 196

// ---------------- scratch (device globals; no runtime allocation) ----------------
__device__ float g_hA[N_NODES * HID];
__device__ float g_hB[N_NODES * HID];
__device__ float g_agg[N_NODES * HID];
__device__ int   g_csr[N_EDGES];
__device__ int   g_cnt[N_NODES];
__device__ int   g_off[N_NODES + 1];
__device__ int   g_wp[N_NODES];
__device__ int   g_bsum[SCAN_NB + 1];
__device__ int   g_is64;

// ---------------- tf32 helpers ----------------
__device__ __forceinline__ uint32_t f2tf32(float f) {
    uint32_t r;
    asm("cvt.rna.tf32.f32 %0, %1;" : "=r"(r) : "f"(f));
    return r;
}
// D += A(tf32) * B(tf32), m16n8k8, fp32 accumulate
__device__ __forceinline__ void mma8(float* d, uint32_t a0, uint32_t a1, uint32_t a2, uint32_t a3,
                                     uint32_t b0, uint32_t b1) {
    asm volatile(
        "mma.sync.aligned.m16n8k8.row.col.f32.tf32.tf32.f32 "
        "{%0,%1,%2,%3},{%4,%5,%6,%7},{%8,%9},{%0,%1,%2,%3};"
        : "+f"(d[0]), "+f"(d[1]), "+f"(d[2]), "+f"(d[3])
        : "r"(a0), "r"(a1), "r"(a2), "r"(a3), "r"(b0), "r"(b1));
}

// ---------------- edge dtype detection ----------------
__global__ void k_detect(const int* __restrict__ e32) {
    if (threadIdx.x == 0) {
        int is64 = 1;
        for (int i = 0; i < 64; i++)
            if (e32[2 * i + 1] != 0) { is64 = 0; break; }
        g_is64 = is64;
    }
}

__device__ __forceinline__ int edge_at(const void* eptr, long long idx, int is64) {
    if (is64) return (int)((const long long*)eptr)[idx];
    return ((const int*)eptr)[idx];
}

// ---------------- CSR build ----------------
__global__ void k_zero_cnt() {
    int i = blockIdx.x * blockDim.x + threadIdx.x;
    if (i < N_NODES) g_cnt[i] = 0;
}

__global__ void k_hist(const void* __restrict__ eptr) {
    long long e = (long long)blockIdx.x * blockDim.x + threadIdx.x;
    if (e >= N_EDGES) return;
    int d = edge_at(eptr, (long long)N_EDGES + e, g_is64);
    atomicAdd(&g_cnt[d], 1);
}

__global__ void k_scan1() {
    __shared__ int s[SCAN_T];
    int t = threadIdx.x;
    int i = blockIdx.x * SCAN_T + t;
    int v = (i < N_NODES) ? g_cnt[i] : 0;
    s[t] = v;
    __syncthreads();
    for (int o = 1; o < SCAN_T; o <<= 1) {
        int add = (t >= o) ? s[t - o] : 0;
        __syncthreads();
        s[t] += add;
        __syncthreads();
    }
    if (i < N_NODES) g_off[i] = s[t] - v;
    if (t == SCAN_T - 1) g_bsum[blockIdx.x] = s[t];
}

__global__ void k_scan2(int nblk) {
    if (threadIdx.x == 0) {
        int acc = 0;
        for (int b = 0; b < nblk; b++) {
            int t = g_bsum[b];
            g_bsum[b] = acc;
            acc += t;
        }
        g_off[N_NODES] = acc;
    }
}

__global__ void k_scan3() {
    int i = blockIdx.x * SCAN_T + threadIdx.x;
    if (i < N_NODES) {
        int v = g_off[i] + g_bsum[blockIdx.x];
        g_off[i] = v;
        g_wp[i] = v;
    }
}

__global__ void k_scatter(const void* __restrict__ eptr) {
    long long e = (long long)blockIdx.x * blockDim.x + threadIdx.x;
    if (e >= N_EDGES) return;
    int is64 = g_is64;
    int s = edge_at(eptr, e, is64);
    int d = edge_at(eptr, (long long)N_EDGES + e, is64);
    int pos = atomicAdd(&g_wp[d], 1);
    g_csr[pos] = s;
}

// ---------------- pre-MLP ----------------
__global__ void k_pre(const float* __restrict__ x, const float* __restrict__ W,
                      const float* __restrict__ b, float* __restrict__ h) {
    int idx = blockIdx.x * blockDim.x + threadIdx.x;
    if (idx >= N_NODES * HID) return;
    int i = idx >> 6, j = idx & 63;
    float acc = b[j]
              + x[i * 3 + 0] * W[j * 3 + 0]
              + x[i * 3 + 1] * W[j * 3 + 1]
              + x[i * 3 + 2] * W[j * 3 + 2];
    h[idx] = fmaxf(acc, 0.0f);
}

// ---------------- aggregation (R1-proven: warp per node, lane owns float2) ----------------
__global__ void __launch_bounds__(256) k_agg(const float* __restrict__ h) {
    int gtid = blockIdx.x * blockDim.x + threadIdx.x;
    int node = gtid >> 5;
    int lane = gtid & 31;
    if (node >= N_NODES) return;
    int s = g_off[node], e = g_off[node + 1];
    const float2* __restrict__ h2 = (const float2*)h;
    float2 acc = make_float2(0.f, 0.f);
    int k = s;
    for (; k + 4 <= e; k += 4) {
        int s0 = g_csr[k + 0], s1 = g_csr[k + 1], s2 = g_csr[k + 2], s3 = g_csr[k + 3];
        float2 v0 = __ldg(&h2[s0 * 32 + lane]);
        float2 v1 = __ldg(&h2[s1 * 32 + lane]);
        float2 v2 = __ldg(&h2[s2 * 32 + lane]);
        float2 v3 = __ldg(&h2[s3 * 32 + lane]);
        acc.x += (v0.x + v1.x) + (v2.x + v3.x);
        acc.y += (v0.y + v1.y) + (v2.y + v3.y);
    }
    for (; k < e; k++) {
        int src = g_csr[k];
        float2 v = __ldg(&h2[src * 32 + lane]);
        acc.x += v.x; acc.y += v.y;
    }
    ((float2*)g_agg)[node * 32 + lane] = acc;
}

// ---------------- transform via tf32 mma.sync (HMMA, non-'a' target OK) -------------------
// hout = relu([agg|hin] @ [relW|rootW].T + relb); LAST fuses post-MLP.
// 3-pass tf32 split: D = Ah*Bh + Al*Bh + Ah*Bl, fp32 register accumulators.
// CTA = 256 thr = 8 warps; warp owns 16 rows; 8 n-tiles of 8; 16 k-steps of 8.
#define BPAD 132
#define SPAD 66
#define XF_SMEM ((2 * 64 * BPAD + 8 * 16 * SPAD) * 4)   // 101376 B

template <int LAST>
__global__ void __launch_bounds__(256) k_xf(
        const float* __restrict__ hin,
        const float* __restrict__ relW, const float* __restrict__ relb,
        const float* __restrict__ rootW,
        const float* __restrict__ postW, const float* __restrict__ postb,
        float* __restrict__ hout) {
    extern __shared__ float smem[];
    float* sBh = smem;                   // [64][BPAD]  tf32(hi) of combined W
    float* sBl = smem + 64 * BPAD;       // [64][BPAD]  tf32(residual)
    float* sSt = smem + 2 * 64 * BPAD;   // LAST: [8 warps][16][SPAD]
    const int tid = threadIdx.x;
    const int warp = tid >> 5;
    const int lane = tid & 31;

    // --- stage combined weights as tf32 hi/lo ---
    for (int f = tid; f < 64 * 128; f += 256) {
        int j = f >> 7, k = f & 127;
        float v = (k < 64) ? relW[j * 64 + k] : rootW[j * 64 + (k - 64)];
        uint32_t hb = f2tf32(v);
        float res = v - __uint_as_float(hb);
        sBh[j * BPAD + k] = __uint_as_float(hb);
        sBl[j * BPAD + k] = __uint_as_float(f2tf32(res));
    }
    __syncthreads();

    // --- fragment row/col ids ---
    const int qr = lane >> 2;            // 0..7
    const int qc = lane & 3;             // 0..3
    const int r0 = blockIdx.x * 128 + warp * 16 + qr;
    const int r1 = r0 + 8;
    const int r0c = (r0 < N_NODES) ? r0 : (N_NODES - 1);
    const int r1c = (r1 < N_NODES) ? r1 : (N_NODES - 1);

    float d[8][4];
#pragma unroll
    for (int nt = 0; nt < 8; nt++)
#pragma unroll
        for (int i = 0; i < 4; i++) d[nt][i] = 0.f;

#pragma unroll 1
    for (int ks = 0; ks < 16; ks++) {
        const float* __restrict__ A = (ks < 8) ? g_agg : hin;
        const int kc = (ks & 7) * 8 + qc;
        float a0 = __ldg(&A[(size_t)r0c * 64 + kc]);
        float a1 = __ldg(&A[(size_t)r1c * 64 + kc]);
        float a2 = __ldg(&A[(size_t)r0c * 64 + kc + 4]);
        float a3 = __ldg(&A[(size_t)r1c * 64 + kc + 4]);
        uint32_t ah0 = f2tf32(a0), ah1 = f2tf32(a1), ah2 = f2tf32(a2), ah3 = f2tf32(a3);
        uint32_t al0 = f2tf32(a0 - __uint_as_float(ah0));
        uint32_t al1 = f2tf32(a1 - __uint_as_float(ah1));
        uint32_t al2 = f2tf32(a2 - __uint_as_float(ah2));
        uint32_t al3 = f2tf32(a3 - __uint_as_float(ah3));

        const int bk = ks * 8 + qc;
#pragma unroll
        for (int nt = 0; nt < 8; nt++) {
            const int bn = nt * 8 + qr;
            uint32_t bh0 = __float_as_uint(sBh[bn * BPAD + bk]);
            uint32_t bh1 = __float_as_uint(sBh[bn * BPAD + bk + 4]);
            uint32_t bl0 = __float_as_uint(sBl[bn * BPAD + bk]);
            uint32_t bl1 = __float_as_uint(sBl[bn * BPAD + bk + 4]);
            mma8(d[nt], ah0, ah1, ah2, ah3, bh0, bh1);
            mma8(d[nt], al0, al1, al2, al3, bh0, bh1);
            mma8(d[nt], ah0, ah1, ah2, ah3, bl0, bl1);
        }
    }

    // --- epilogue ---
    if (!LAST) {
#pragma unroll
        for (int nt = 0; nt < 8; nt++) {
            const int col = nt * 8 + 2 * qc;
            const float bx = __ldg(&relb[col]);
            const float by = __ldg(&relb[col + 1]);
            if (r0 < N_NODES) {
                float2 o = make_float2(fmaxf(d[nt][0] + bx, 0.f), fmaxf(d[nt][1] + by, 0.f));
                *(float2*)&hout[(size_t)r0 * 64 + col] = o;
            }
            if (r1 < N_NODES) {
                float2 o = make_float2(fmaxf(d[nt][2] + bx, 0.f), fmaxf(d[nt][3] + by, 0.f));
                *(float2*)&hout[(size_t)r1 * 64 + col] = o;
            }
        }
    } else {
        // stage relu(h3) rows into per-warp smem, then fused post-MLP
        float* st = sSt + warp * 16 * SPAD;
#pragma unroll
        for (int nt = 0; nt < 8; nt++) {
            const int col = nt * 8 + 2 * qc;
            const float bx = __ldg(&relb[col]);
            const float by = __ldg(&relb[col + 1]);
            st[qr * SPAD + col]           = fmaxf(d[nt][0] + bx, 0.f);
            st[qr * SPAD + col + 1]       = fmaxf(d[nt][1] + by, 0.f);
            st[(qr + 8) * SPAD + col]     = fmaxf(d[nt][2] + bx, 0.f);
            st[(qr + 8) * SPAD + col + 1] = fmaxf(d[nt][3] + by, 0.f);
        }
        __syncwarp();
        if (lane < 16) {
            const int gr = blockIdx.x * 128 + warp * 16 + lane;
            if (gr < N_NODES) {
                float o0 = __ldg(&postb[0]), o1 = __ldg(&postb[1]);
                const float* row = &st[lane * SPAD];
#pragma unroll 8
                for (int c = 0; c < 64; c++) {
                    float v = row[c];
                    o0 += v * __ldg(&postW[c]);
                    o1 += v * __ldg(&postW[64 + c]);
                }
                hout[2 * gr + 0] = fmaxf(o0, 0.f);
                hout[2 * gr + 1] = fmaxf(o1, 0.f);
            }
        }
    }
}

// ---------------- launch ----------------
extern "C" void kernel_launch(void* const* d_in, const int* in_sizes, int n_in,
                              void* d_out, int out_size) {
    const float* x     = (const float*)d_in[0];
    const void*  ei    = d_in[1];
    const float* preW  = (const float*)d_in[2];
    const float* preb  = (const float*)d_in[3];
    const float* postW = (const float*)d_in[4];
    const float* postb = (const float*)d_in[5];
    const float* relW[3]  = {(const float*)d_in[6],  (const float*)d_in[9],  (const float*)d_in[12]};
    const float* relb[3]  = {(const float*)d_in[7],  (const float*)d_in[10], (const float*)d_in[13]};
    const float* rootW[3] = {(const float*)d_in[8],  (const float*)d_in[11], (const float*)d_in[14]};
    float* out = (float*)d_out;

    cudaFuncSetAttribute(k_xf<0>, cudaFuncAttributeMaxDynamicSharedMemorySize, XF_SMEM);
    cudaFuncSetAttribute(k_xf<1>, cudaFuncAttributeMaxDynamicSharedMemorySize, XF_SMEM);

    float *hA, *hB;
    cudaGetSymbolAddress((void**)&hA, g_hA);
    cudaGetSymbolAddress((void**)&hB, g_hB);

    // CSR build
    k_detect<<<1, 32>>>((const int*)ei);
    k_zero_cnt<<<(N_NODES + 255) / 256, 256>>>();
    k_hist<<<(N_EDGES + 255) / 256, 256>>>(ei);
    k_scan1<<<SCAN_NB, SCAN_T>>>();
    k_scan2<<<1, 32>>>(SCAN_NB);
    k_scan3<<<SCAN_NB, SCAN_T>>>();
    k_scatter<<<(N_EDGES + 255) / 256, 256>>>(ei);

    // pre-MLP
    k_pre<<<(N_NODES * HID + 255) / 256, 256>>>(x, preW, preb, hA);

    const int agg_blocks = (N_NODES * 32 + 255) / 256;
    const int xf_blocks  = (N_NODES + 127) / 128;

    // layer 0: hA -> hB ; layer 1: hB -> hA ; layer 2 (last, fused post): hA -> out
    k_agg<<<agg_blocks, 256>>>(hA);
    k_xf<0><<<xf_blocks, 256, XF_SMEM>>>(hA, relW[0], relb[0], rootW[0], postW, postb, hB);
    k_agg<<<agg_blocks, 256>>>(hB);
    k_xf<0><<<xf_blocks, 256, XF_SMEM>>>(hB, relW[1], relb[1], rootW[1], postW, postb, hA);
    k_agg<<<agg_blocks, 256>>>(hA);
    k_xf<1><<<xf_blocks, 256, XF_SMEM>>>(hA, relW[2], relb[2], rootW[2], postW, postb, out);
}

// round 7
// speedup vs baseline: 1.7063x; 1.0810x over previous
#include <cuda_runtime.h>
#include <cuda_fp16.h>
#include <cstdint>

#define N_NODES 100000
#define N_EDGES 1600000
#define HID 64
#define SCAN_T 512
#define SCAN_NB ((N_NODES + SCAN_T - 1) / SCAN_T)   // 196

// ---------------- scratch (device globals; no runtime allocation) ----------------
__device__ float  g_hA[N_NODES * HID];
__device__ float  g_hB[N_NODES * HID];
__device__ __half g_h16A[N_NODES * HID];
__device__ __half g_h16B[N_NODES * HID];
__device__ float  g_agg[N_NODES * HID];
__device__ int    g_csr[N_EDGES];
__device__ int    g_cnt[N_NODES];
__device__ int    g_off[N_NODES + 1];
__device__ int    g_wp[N_NODES];
__device__ int    g_bsum[SCAN_NB + 1];
__device__ int    g_is64;

// ---------------- tf32 helpers ----------------
__device__ __forceinline__ uint32_t f2tf32(float f) {
    uint32_t r;
    asm("cvt.rna.tf32.f32 %0, %1;" : "=r"(r) : "f"(f));
    return r;
}
__device__ __forceinline__ void mma8(float* d, uint32_t a0, uint32_t a1, uint32_t a2, uint32_t a3,
                                     uint32_t b0, uint32_t b1) {
    asm volatile(
        "mma.sync.aligned.m16n8k8.row.col.f32.tf32.tf32.f32 "
        "{%0,%1,%2,%3},{%4,%5,%6,%7},{%8,%9},{%0,%1,%2,%3};"
        : "+f"(d[0]), "+f"(d[1]), "+f"(d[2]), "+f"(d[3])
        : "r"(a0), "r"(a1), "r"(a2), "r"(a3), "r"(b0), "r"(b1));
}

// ---------------- edge dtype detection (warp-parallel) ----------------
__global__ void k_detect(const int* __restrict__ e32) {
    int lane = threadIdx.x;
    int bad = 0;
    for (int i = lane; i < 64; i += 32)
        if (e32[2 * i + 1] != 0) bad = 1;
    unsigned m = __ballot_sync(0xFFFFFFFFu, bad);
    if (lane == 0) g_is64 = (m == 0) ? 1 : 0;
}

__device__ __forceinline__ int edge_at(const void* eptr, long long idx, int is64) {
    if (is64) return (int)((const long long*)eptr)[idx];
    return ((const int*)eptr)[idx];
}

// ---------------- CSR build ----------------
__global__ void k_zero_cnt() {
    int i = blockIdx.x * blockDim.x + threadIdx.x;
    if (i < N_NODES) g_cnt[i] = 0;
}

__global__ void k_hist(const void* __restrict__ eptr) {
    long long e = (long long)blockIdx.x * blockDim.x + threadIdx.x;
    if (e >= N_EDGES) return;
    int d = edge_at(eptr, (long long)N_EDGES + e, g_is64);
    atomicAdd(&g_cnt[d], 1);
}

__global__ void k_scan1() {
    __shared__ int s[SCAN_T];
    int t = threadIdx.x;
    int i = blockIdx.x * SCAN_T + t;
    int v = (i < N_NODES) ? g_cnt[i] : 0;
    s[t] = v;
    __syncthreads();
    for (int o = 1; o < SCAN_T; o <<= 1) {
        int add = (t >= o) ? s[t - o] : 0;
        __syncthreads();
        s[t] += add;
        __syncthreads();
    }
    if (i < N_NODES) g_off[i] = s[t] - v;
    if (t == SCAN_T - 1) g_bsum[blockIdx.x] = s[t];
}

// warp-parallel scan over the 196 block sums
__global__ void k_scan2() {
    int lane = threadIdx.x;
    int carry = 0;
    for (int base = 0; base < SCAN_NB; base += 32) {
        int i = base + lane;
        int v0 = (i < SCAN_NB) ? g_bsum[i] : 0;
        int v = v0;
#pragma unroll
        for (int o = 1; o < 32; o <<= 1) {
            int t = __shfl_up_sync(0xFFFFFFFFu, v, o);
            if (lane >= o) v += t;
        }
        if (i < SCAN_NB) g_bsum[i] = carry + (v - v0);   // exclusive + carry
        carry += __shfl_sync(0xFFFFFFFFu, v, 31);
    }
    if (lane == 0) g_off[N_NODES] = carry;
}

__global__ void k_scan3() {
    int i = blockIdx.x * SCAN_T + threadIdx.x;
    if (i < N_NODES) {
        int v = g_off[i] + g_bsum[blockIdx.x];
        g_off[i] = v;
        g_wp[i] = v;
    }
}

__global__ void k_scatter(const void* __restrict__ eptr) {
    long long e = (long long)blockIdx.x * blockDim.x + threadIdx.x;
    if (e >= N_EDGES) return;
    int is64 = g_is64;
    int s = edge_at(eptr, e, is64);
    int d = edge_at(eptr, (long long)N_EDGES + e, is64);
    int pos = atomicAdd(&g_wp[d], 1);
    g_csr[pos] = s;
}

// ---------------- pre-MLP (writes fp32 + fp16 copies) ----------------
__global__ void k_pre(const float* __restrict__ x, const float* __restrict__ W,
                      const float* __restrict__ b, float* __restrict__ h,
                      __half* __restrict__ h16) {
    int idx = blockIdx.x * blockDim.x + threadIdx.x;
    if (idx >= N_NODES * HID) return;
    int i = idx >> 6, j = idx & 63;
    float acc = b[j]
              + x[i * 3 + 0] * W[j * 3 + 0]
              + x[i * 3 + 1] * W[j * 3 + 1]
              + x[i * 3 + 2] * W[j * 3 + 2];
    float r = fmaxf(acc, 0.0f);
    h[idx] = r;
    h16[idx] = __float2half(r);
}

// ---------------- aggregation: fp16 gather, fp32 accumulate ----------------
// half-warp (16 lanes) per node; lane owns 4 halves (8B) -> 128B row per edge
__global__ void __launch_bounds__(256) k_agg(const __half* __restrict__ h16) {
    int gtid = blockIdx.x * blockDim.x + threadIdx.x;
    int node = gtid >> 4;
    int sub = gtid & 15;
    if (node >= N_NODES) return;
    int s = g_off[node], e = g_off[node + 1];
    const uint2* __restrict__ hv = (const uint2*)h16;   // 4 halves per uint2
    float4 acc = make_float4(0.f, 0.f, 0.f, 0.f);
    int k = s;
    for (; k + 4 <= e; k += 4) {
        int s0 = g_csr[k + 0], s1 = g_csr[k + 1], s2 = g_csr[k + 2], s3 = g_csr[k + 3];
        uint2 r0 = __ldg(&hv[s0 * 16 + sub]);
        uint2 r1 = __ldg(&hv[s1 * 16 + sub]);
        uint2 r2 = __ldg(&hv[s2 * 16 + sub]);
        uint2 r3 = __ldg(&hv[s3 * 16 + sub]);
#pragma unroll
        for (int q = 0; q < 4; q++) {
            uint2 raw = (q == 0) ? r0 : (q == 1) ? r1 : (q == 2) ? r2 : r3;
            float2 f0 = __half22float2(*(__half2*)&raw.x);
            float2 f1 = __half22float2(*(__half2*)&raw.y);
            acc.x += f0.x; acc.y += f0.y; acc.z += f1.x; acc.w += f1.y;
        }
    }
    for (; k < e; k++) {
        uint2 raw = __ldg(&hv[g_csr[k] * 16 + sub]);
        float2 f0 = __half22float2(*(__half2*)&raw.x);
        float2 f1 = __half22float2(*(__half2*)&raw.y);
        acc.x += f0.x; acc.y += f0.y; acc.z += f1.x; acc.w += f1.y;
    }
    ((float4*)g_agg)[node * 16 + sub] = acc;
}

// ---------------- transform via tf32 mma.sync -------------------
#define BPAD 132
#define SPAD 66
#define XF_SMEM ((2 * 64 * BPAD + 8 * 16 * SPAD) * 4)   // 101376 B

template <int LAST>
__global__ void __launch_bounds__(256) k_xf(
        const float* __restrict__ hin,
        const float* __restrict__ relW, const float* __restrict__ relb,
        const float* __restrict__ rootW,
        const float* __restrict__ postW, const float* __restrict__ postb,
        float* __restrict__ hout, __half* __restrict__ hout16) {
    extern __shared__ float smem[];
    float* sBh = smem;                   // [64][BPAD] tf32(hi)
    float* sBl = smem + 64 * BPAD;       // [64][BPAD] tf32(residual)
    float* sSt = smem + 2 * 64 * BPAD;   // LAST: [8 warps][16][SPAD]
    const int tid = threadIdx.x;
    const int warp = tid >> 5;
    const int lane = tid & 31;

    for (int f = tid; f < 64 * 128; f += 256) {
        int j = f >> 7, k = f & 127;
        float v = (k < 64) ? relW[j * 64 + k] : rootW[j * 64 + (k - 64)];
        uint32_t hb = f2tf32(v);
        float res = v - __uint_as_float(hb);
        sBh[j * BPAD + k] = __uint_as_float(hb);
        sBl[j * BPAD + k] = __uint_as_float(f2tf32(res));
    }
    __syncthreads();

    const int qr = lane >> 2;
    const int qc = lane & 3;
    const int r0 = blockIdx.x * 128 + warp * 16 + qr;
    const int r1 = r0 + 8;
    const int r0c = (r0 < N_NODES) ? r0 : (N_NODES - 1);
    const int r1c = (r1 < N_NODES) ? r1 : (N_NODES - 1);

    float d[8][4];
#pragma unroll
    for (int nt = 0; nt < 8; nt++)
#pragma unroll
        for (int i = 0; i < 4; i++) d[nt][i] = 0.f;

#pragma unroll 1
    for (int ks = 0; ks < 16; ks++) {
        const float* __restrict__ A = (ks < 8) ? g_agg : hin;
        const int kc = (ks & 7) * 8 + qc;
        float a0 = __ldg(&A[(size_t)r0c * 64 + kc]);
        float a1 = __ldg(&A[(size_t)r1c * 64 + kc]);
        float a2 = __ldg(&A[(size_t)r0c * 64 + kc + 4]);
        float a3 = __ldg(&A[(size_t)r1c * 64 + kc + 4]);
        uint32_t ah0 = f2tf32(a0), ah1 = f2tf32(a1), ah2 = f2tf32(a2), ah3 = f2tf32(a3);
        uint32_t al0 = f2tf32(a0 - __uint_as_float(ah0));
        uint32_t al1 = f2tf32(a1 - __uint_as_float(ah1));
        uint32_t al2 = f2tf32(a2 - __uint_as_float(ah2));
        uint32_t al3 = f2tf32(a3 - __uint_as_float(ah3));

        const int bk = ks * 8 + qc;
#pragma unroll
        for (int nt = 0; nt < 8; nt++) {
            const int bn = nt * 8 + qr;
            uint32_t bh0 = __float_as_uint(sBh[bn * BPAD + bk]);
            uint32_t bh1 = __float_as_uint(sBh[bn * BPAD + bk + 4]);
            uint32_t bl0 = __float_as_uint(sBl[bn * BPAD + bk]);
            uint32_t bl1 = __float_as_uint(sBl[bn * BPAD + bk + 4]);
            mma8(d[nt], ah0, ah1, ah2, ah3, bh0, bh1);
            mma8(d[nt], al0, al1, al2, al3, bh0, bh1);
            mma8(d[nt], ah0, ah1, ah2, ah3, bl0, bl1);
        }
    }

    if (!LAST) {
#pragma unroll
        for (int nt = 0; nt < 8; nt++) {
            const int col = nt * 8 + 2 * qc;
            const float bx = __ldg(&relb[col]);
            const float by = __ldg(&relb[col + 1]);
            if (r0 < N_NODES) {
                float vx = fmaxf(d[nt][0] + bx, 0.f), vy = fmaxf(d[nt][1] + by, 0.f);
                *(float2*)&hout[(size_t)r0 * 64 + col] = make_float2(vx, vy);
                *(__half2*)&hout16[(size_t)r0 * 64 + col] = __floats2half2_rn(vx, vy);
            }
            if (r1 < N_NODES) {
                float vx = fmaxf(d[nt][2] + bx, 0.f), vy = fmaxf(d[nt][3] + by, 0.f);
                *(float2*)&hout[(size_t)r1 * 64 + col] = make_float2(vx, vy);
                *(__half2*)&hout16[(size_t)r1 * 64 + col] = __floats2half2_rn(vx, vy);
            }
        }
    } else {
        float* st = sSt + warp * 16 * SPAD;
#pragma unroll
        for (int nt = 0; nt < 8; nt++) {
            const int col = nt * 8 + 2 * qc;
            const float bx = __ldg(&relb[col]);
            const float by = __ldg(&relb[col + 1]);
            st[qr * SPAD + col]           = fmaxf(d[nt][0] + bx, 0.f);
            st[qr * SPAD + col + 1]       = fmaxf(d[nt][1] + by, 0.f);
            st[(qr + 8) * SPAD + col]     = fmaxf(d[nt][2] + bx, 0.f);
            st[(qr + 8) * SPAD + col + 1] = fmaxf(d[nt][3] + by, 0.f);
        }
        __syncwarp();
        if (lane < 16) {
            const int gr = blockIdx.x * 128 + warp * 16 + lane;
            if (gr < N_NODES) {
                float o0 = __ldg(&postb[0]), o1 = __ldg(&postb[1]);
                const float* row = &st[lane * SPAD];
#pragma unroll 8
                for (int c = 0; c < 64; c++) {
                    float v = row[c];
                    o0 += v * __ldg(&postW[c]);
                    o1 += v * __ldg(&postW[64 + c]);
                }
                hout[2 * gr + 0] = fmaxf(o0, 0.f);
                hout[2 * gr + 1] = fmaxf(o1, 0.f);
            }
        }
    }
}

// ---------------- launch ----------------
extern "C" void kernel_launch(void* const* d_in, const int* in_sizes, int n_in,
                              void* d_out, int out_size) {
    const float* x     = (const float*)d_in[0];
    const void*  ei    = d_in[1];
    const float* preW  = (const float*)d_in[2];
    const float* preb  = (const float*)d_in[3];
    const float* postW = (const float*)d_in[4];
    const float* postb = (const float*)d_in[5];
    const float* relW[3]  = {(const float*)d_in[6],  (const float*)d_in[9],  (const float*)d_in[12]};
    const float* relb[3]  = {(const float*)d_in[7],  (const float*)d_in[10], (const float*)d_in[13]};
    const float* rootW[3] = {(const float*)d_in[8],  (const float*)d_in[11], (const float*)d_in[14]};
    float* out = (float*)d_out;

    cudaFuncSetAttribute(k_xf<0>, cudaFuncAttributeMaxDynamicSharedMemorySize, XF_SMEM);
    cudaFuncSetAttribute(k_xf<1>, cudaFuncAttributeMaxDynamicSharedMemorySize, XF_SMEM);

    float *hA, *hB;
    __half *h16A, *h16B;
    cudaGetSymbolAddress((void**)&hA, g_hA);
    cudaGetSymbolAddress((void**)&hB, g_hB);
    cudaGetSymbolAddress((void**)&h16A, g_h16A);
    cudaGetSymbolAddress((void**)&h16B, g_h16B);

    // CSR build
    k_detect<<<1, 32>>>((const int*)ei);
    k_zero_cnt<<<(N_NODES + 255) / 256, 256>>>();
    k_hist<<<(N_EDGES + 255) / 256, 256>>>(ei);
    k_scan1<<<SCAN_NB, SCAN_T>>>();
    k_scan2<<<1, 32>>>();
    k_scan3<<<SCAN_NB, SCAN_T>>>();
    k_scatter<<<(N_EDGES + 255) / 256, 256>>>(ei);

    // pre-MLP
    k_pre<<<(N_NODES * HID + 255) / 256, 256>>>(x, preW, preb, hA, h16A);

    const int agg_blocks = (N_NODES * 16 + 255) / 256;
    const int xf_blocks  = (N_NODES + 127) / 128;

    // layer 0: A -> B ; layer 1: B -> A ; layer 2 (last, fused post): A -> out
    k_agg<<<agg_blocks, 256>>>(h16A);
    k_xf<0><<<xf_blocks, 256, XF_SMEM>>>(hA, relW[0], relb[0], rootW[0], postW, postb, hB, h16B);
    k_agg<<<agg_blocks, 256>>>(h16B);
    k_xf<0><<<xf_blocks, 256, XF_SMEM>>>(hB, relW[1], relb[1], rootW[1], postW, postb, hA, h16A);
    k_agg<<<agg_blocks, 256>>>(h16A);
    k_xf<1><<<xf_blocks, 256, XF_SMEM>>>(hA, relW[2], relb[2], rootW[2], postW, postb, out, h16B);
}

// round 8
// speedup vs baseline: 2.0577x; 1.2060x over previous
#include <cuda_runtime.h>
#include <cuda_fp16.h>
#include <cstdint>

#define N_NODES 100000
#define N_EDGES 1600000
#define HID 64
#define SCAN_T 512
#define SCAN_NB ((N_NODES + SCAN_T - 1) / SCAN_T)   // 196

// ---------------- scratch (device globals; no runtime allocation) ----------------
__device__ float  g_hA[N_NODES * HID];
__device__ float  g_hB[N_NODES * HID];
__device__ __half g_h16A[N_NODES * HID];
__device__ __half g_h16B[N_NODES * HID];
__device__ float  g_agg[N_NODES * HID];
__device__ int    g_csr[N_EDGES];
__device__ int    g_cnt[N_NODES];
__device__ int    g_off[N_NODES + 1];
__device__ int    g_wp[N_NODES];
__device__ int    g_bsum[SCAN_NB + 1];
__device__ int    g_is64;

// ---------------- fp16 mma helpers ----------------
__device__ __forceinline__ uint32_t pkh(float x, float y) {
    __half2 h = __floats2half2_rn(x, y);
    return *(uint32_t*)&h;
}
__device__ __forceinline__ uint32_t pklo(float x, float y, uint32_t hi) {
    __half2 h = *(__half2*)&hi;
    float2 hf = __half22float2(h);
    __half2 l = __floats2half2_rn(x - hf.x, y - hf.y);
    return *(uint32_t*)&l;
}
// D += A(f16) * B(f16), m16n8k16, fp32 accumulate
__device__ __forceinline__ void mma16(float* d, uint32_t a0, uint32_t a1, uint32_t a2, uint32_t a3,
                                      uint32_t b0, uint32_t b1) {
    asm volatile(
        "mma.sync.aligned.m16n8k16.row.col.f32.f16.f16.f32 "
        "{%0,%1,%2,%3},{%4,%5,%6,%7},{%8,%9},{%0,%1,%2,%3};"
        : "+f"(d[0]), "+f"(d[1]), "+f"(d[2]), "+f"(d[3])
        : "r"(a0), "r"(a1), "r"(a2), "r"(a3), "r"(b0), "r"(b1));
}

// ---------------- edge dtype detection (warp-parallel) ----------------
__global__ void k_detect(const int* __restrict__ e32) {
    int lane = threadIdx.x;
    int bad = 0;
    for (int i = lane; i < 64; i += 32)
        if (e32[2 * i + 1] != 0) bad = 1;
    unsigned m = __ballot_sync(0xFFFFFFFFu, bad);
    if (lane == 0) g_is64 = (m == 0) ? 1 : 0;
}

__device__ __forceinline__ int edge_at(const void* eptr, long long idx, int is64) {
    if (is64) return (int)((const long long*)eptr)[idx];
    return ((const int*)eptr)[idx];
}

// ---------------- CSR build ----------------
__global__ void k_zero_cnt() {
    int i = blockIdx.x * blockDim.x + threadIdx.x;
    if (i < N_NODES) g_cnt[i] = 0;
}

__global__ void k_hist(const void* __restrict__ eptr) {
    long long e = (long long)blockIdx.x * blockDim.x + threadIdx.x;
    if (e >= N_EDGES) return;
    int d = edge_at(eptr, (long long)N_EDGES + e, g_is64);
    atomicAdd(&g_cnt[d], 1);
}

__global__ void k_scan1() {
    __shared__ int s[SCAN_T];
    int t = threadIdx.x;
    int i = blockIdx.x * SCAN_T + t;
    int v = (i < N_NODES) ? g_cnt[i] : 0;
    s[t] = v;
    __syncthreads();
    for (int o = 1; o < SCAN_T; o <<= 1) {
        int add = (t >= o) ? s[t - o] : 0;
        __syncthreads();
        s[t] += add;
        __syncthreads();
    }
    if (i < N_NODES) g_off[i] = s[t] - v;
    if (t == SCAN_T - 1) g_bsum[blockIdx.x] = s[t];
}

// warp-parallel scan over the 196 block sums
__global__ void k_scan2() {
    int lane = threadIdx.x;
    int carry = 0;
    for (int base = 0; base < SCAN_NB; base += 32) {
        int i = base + lane;
        int v0 = (i < SCAN_NB) ? g_bsum[i] : 0;
        int v = v0;
#pragma unroll
        for (int o = 1; o < 32; o <<= 1) {
            int t = __shfl_up_sync(0xFFFFFFFFu, v, o);
            if (lane >= o) v += t;
        }
        if (i < SCAN_NB) g_bsum[i] = carry + (v - v0);   // exclusive + carry
        carry += __shfl_sync(0xFFFFFFFFu, v, 31);
    }
    if (lane == 0) g_off[N_NODES] = carry;
}

__global__ void k_scan3() {
    int i = blockIdx.x * SCAN_T + threadIdx.x;
    if (i < N_NODES) {
        int v = g_off[i] + g_bsum[blockIdx.x];
        g_off[i] = v;
        g_wp[i] = v;
    }
}

__global__ void k_scatter(const void* __restrict__ eptr) {
    long long e = (long long)blockIdx.x * blockDim.x + threadIdx.x;
    if (e >= N_EDGES) return;
    int is64 = g_is64;
    int s = edge_at(eptr, e, is64);
    int d = edge_at(eptr, (long long)N_EDGES + e, is64);
    int pos = atomicAdd(&g_wp[d], 1);
    g_csr[pos] = s;
}

// ---------------- pre-MLP (writes fp32 + fp16 copies) ----------------
__global__ void k_pre(const float* __restrict__ x, const float* __restrict__ W,
                      const float* __restrict__ b, float* __restrict__ h,
                      __half* __restrict__ h16) {
    int idx = blockIdx.x * blockDim.x + threadIdx.x;
    if (idx >= N_NODES * HID) return;
    int i = idx >> 6, j = idx & 63;
    float acc = b[j]
              + x[i * 3 + 0] * W[j * 3 + 0]
              + x[i * 3 + 1] * W[j * 3 + 1]
              + x[i * 3 + 2] * W[j * 3 + 2];
    float r = fmaxf(acc, 0.0f);
    h[idx] = r;
    h16[idx] = __float2half(r);
}

// ---------------- aggregation: fp16 gather, fp32 accumulate ----------------
// half-warp (16 lanes) per node; lane owns 4 halves (8B) -> 128B row per edge
__global__ void __launch_bounds__(256) k_agg(const __half* __restrict__ h16) {
    int gtid = blockIdx.x * blockDim.x + threadIdx.x;
    int node = gtid >> 4;
    int sub = gtid & 15;
    if (node >= N_NODES) return;
    int s = g_off[node], e = g_off[node + 1];
    const uint2* __restrict__ hv = (const uint2*)h16;
    float4 acc = make_float4(0.f, 0.f, 0.f, 0.f);
    int k = s;
    for (; k + 4 <= e; k += 4) {
        int s0 = g_csr[k + 0], s1 = g_csr[k + 1], s2 = g_csr[k + 2], s3 = g_csr[k + 3];
        uint2 r0 = __ldg(&hv[s0 * 16 + sub]);
        uint2 r1 = __ldg(&hv[s1 * 16 + sub]);
        uint2 r2 = __ldg(&hv[s2 * 16 + sub]);
        uint2 r3 = __ldg(&hv[s3 * 16 + sub]);
#pragma unroll
        for (int q = 0; q < 4; q++) {
            uint2 raw = (q == 0) ? r0 : (q == 1) ? r1 : (q == 2) ? r2 : r3;
            float2 f0 = __half22float2(*(__half2*)&raw.x);
            float2 f1 = __half22float2(*(__half2*)&raw.y);
            acc.x += f0.x; acc.y += f0.y; acc.z += f1.x; acc.w += f1.y;
        }
    }
    for (; k < e; k++) {
        uint2 raw = __ldg(&hv[g_csr[k] * 16 + sub]);
        float2 f0 = __half22float2(*(__half2*)&raw.x);
        float2 f1 = __half22float2(*(__half2*)&raw.y);
        acc.x += f0.x; acc.y += f0.y; acc.z += f1.x; acc.w += f1.y;
    }
    ((float4*)g_agg)[node * 16 + sub] = acc;
}

// ---------------- transform via fp16 m16n8k16 mma (hi/lo split, 3 passes) ----------------
// hout = relu([agg|hin] @ [relW|rootW].T + relb); LAST fuses post-MLP.
// D = Ah*Bh + Al*Bh + Ah*Bl, fp32 accumulators; split error ~1e-6.
#define WPAD 68   // uint stride: (bn*68 + kb) % 32 = bn*4 + kb -> lane-distinct banks
#define SPAD 66
#define XF_SMEM0 (2 * 64 * WPAD * 4)                       // 34816 B
#define XF_SMEM1 (2 * 64 * WPAD * 4 + 8 * 16 * SPAD * 4)   // 68608 B

template <int LAST>
__global__ void __launch_bounds__(256) k_xf(
        const float* __restrict__ hin,
        const float* __restrict__ relW, const float* __restrict__ relb,
        const float* __restrict__ rootW,
        const float* __restrict__ postW, const float* __restrict__ postb,
        float* __restrict__ hout, __half* __restrict__ hout16) {
    extern __shared__ uint32_t smemu[];
    uint32_t* sBh = smemu;                 // [64 n][64 kp] packed half2, stride WPAD
    uint32_t* sBl = smemu + 64 * WPAD;
    float* sSt = (float*)(smemu + 2 * 64 * WPAD);   // LAST only
    const int tid = threadIdx.x;
    const int warp = tid >> 5;
    const int lane = tid & 31;

    // --- stage combined weights as packed half2 hi/lo: entry [n][kp] = (W[n][2kp], W[n][2kp+1]) ---
    for (int f = tid; f < 64 * 64; f += 256) {
        int n = f >> 6, kp = f & 63;
        int k = kp * 2;   // even; pair never straddles the rel/root boundary
        const float* src = (k < 64) ? &relW[n * 64 + k] : &rootW[n * 64 + (k - 64)];
        float2 v = *(const float2*)src;
        uint32_t hi = pkh(v.x, v.y);
        sBh[n * WPAD + kp] = hi;
        sBl[n * WPAD + kp] = pklo(v.x, v.y, hi);
    }
    __syncthreads();

    const int qr = lane >> 2;   // 0..7
    const int qc = lane & 3;    // 0..3
    const int r0 = blockIdx.x * 128 + warp * 16 + qr;
    const int r1 = r0 + 8;
    const int r0c = (r0 < N_NODES) ? r0 : (N_NODES - 1);
    const int r1c = (r1 < N_NODES) ? r1 : (N_NODES - 1);

    float d[8][4];
#pragma unroll
    for (int nt = 0; nt < 8; nt++)
#pragma unroll
        for (int i = 0; i < 4; i++) d[nt][i] = 0.f;

#pragma unroll 1
    for (int ks = 0; ks < 8; ks++) {
        const float* __restrict__ A = (ks < 4) ? g_agg : hin;
        const int kc = (ks & 3) * 16 + 2 * qc;
        float2 f0 = *(const float2*)&A[(size_t)r0c * 64 + kc];       // a0: row qr,  k 0..7 of chunk
        float2 f1 = *(const float2*)&A[(size_t)r1c * 64 + kc];       // a1: row qr+8,k 0..7
        float2 f2 = *(const float2*)&A[(size_t)r0c * 64 + kc + 8];   // a2: row qr,  k 8..15
        float2 f3 = *(const float2*)&A[(size_t)r1c * 64 + kc + 8];   // a3: row qr+8,k 8..15
        uint32_t ah0 = pkh(f0.x, f0.y), ah1 = pkh(f1.x, f1.y);
        uint32_t ah2 = pkh(f2.x, f2.y), ah3 = pkh(f3.x, f3.y);
        uint32_t al0 = pklo(f0.x, f0.y, ah0), al1 = pklo(f1.x, f1.y, ah1);
        uint32_t al2 = pklo(f2.x, f2.y, ah2), al3 = pklo(f3.x, f3.y, ah3);

        const int kb = ks * 8 + qc;
#pragma unroll
        for (int nt = 0; nt < 8; nt++) {
            const int bn = nt * 8 + qr;
            uint32_t bh0 = sBh[bn * WPAD + kb];
            uint32_t bh1 = sBh[bn * WPAD + kb + 4];
            uint32_t bl0 = sBl[bn * WPAD + kb];
            uint32_t bl1 = sBl[bn * WPAD + kb + 4];
            mma16(d[nt], ah0, ah1, ah2, ah3, bh0, bh1);
            mma16(d[nt], al0, al1, al2, al3, bh0, bh1);
            mma16(d[nt], ah0, ah1, ah2, ah3, bl0, bl1);
        }
    }

    if (!LAST) {
#pragma unroll
        for (int nt = 0; nt < 8; nt++) {
            const int col = nt * 8 + 2 * qc;
            const float bx = __ldg(&relb[col]);
            const float by = __ldg(&relb[col + 1]);
            if (r0 < N_NODES) {
                float vx = fmaxf(d[nt][0] + bx, 0.f), vy = fmaxf(d[nt][1] + by, 0.f);
                *(float2*)&hout[(size_t)r0 * 64 + col] = make_float2(vx, vy);
                *(__half2*)&hout16[(size_t)r0 * 64 + col] = __floats2half2_rn(vx, vy);
            }
            if (r1 < N_NODES) {
                float vx = fmaxf(d[nt][2] + bx, 0.f), vy = fmaxf(d[nt][3] + by, 0.f);
                *(float2*)&hout[(size_t)r1 * 64 + col] = make_float2(vx, vy);
                *(__half2*)&hout16[(size_t)r1 * 64 + col] = __floats2half2_rn(vx, vy);
            }
        }
    } else {
        float* st = sSt + warp * 16 * SPAD;
#pragma unroll
        for (int nt = 0; nt < 8; nt++) {
            const int col = nt * 8 + 2 * qc;
            const float bx = __ldg(&relb[col]);
            const float by = __ldg(&relb[col + 1]);
            st[qr * SPAD + col]           = fmaxf(d[nt][0] + bx, 0.f);
            st[qr * SPAD + col + 1]       = fmaxf(d[nt][1] + by, 0.f);
            st[(qr + 8) * SPAD + col]     = fmaxf(d[nt][2] + bx, 0.f);
            st[(qr + 8) * SPAD + col + 1] = fmaxf(d[nt][3] + by, 0.f);
        }
        __syncwarp();
        if (lane < 16) {
            const int gr = blockIdx.x * 128 + warp * 16 + lane;
            if (gr < N_NODES) {
                float o0 = __ldg(&postb[0]), o1 = __ldg(&postb[1]);
                const float* row = &st[lane * SPAD];
#pragma unroll 8
                for (int c = 0; c < 64; c++) {
                    float v = row[c];
                    o0 += v * __ldg(&postW[c]);
                    o1 += v * __ldg(&postW[64 + c]);
                }
                hout[2 * gr + 0] = fmaxf(o0, 0.f);
                hout[2 * gr + 1] = fmaxf(o1, 0.f);
            }
        }
    }
}

// ---------------- launch ----------------
extern "C" void kernel_launch(void* const* d_in, const int* in_sizes, int n_in,
                              void* d_out, int out_size) {
    const float* x     = (const float*)d_in[0];
    const void*  ei    = d_in[1];
    const float* preW  = (const float*)d_in[2];
    const float* preb  = (const float*)d_in[3];
    const float* postW = (const float*)d_in[4];
    const float* postb = (const float*)d_in[5];
    const float* relW[3]  = {(const float*)d_in[6],  (const float*)d_in[9],  (const float*)d_in[12]};
    const float* relb[3]  = {(const float*)d_in[7],  (const float*)d_in[10], (const float*)d_in[13]};
    const float* rootW[3] = {(const float*)d_in[8],  (const float*)d_in[11], (const float*)d_in[14]};
    float* out = (float*)d_out;

    cudaFuncSetAttribute(k_xf<0>, cudaFuncAttributeMaxDynamicSharedMemorySize, XF_SMEM0);
    cudaFuncSetAttribute(k_xf<1>, cudaFuncAttributeMaxDynamicSharedMemorySize, XF_SMEM1);

    float *hA, *hB;
    __half *h16A, *h16B;
    cudaGetSymbolAddress((void**)&hA, g_hA);
    cudaGetSymbolAddress((void**)&hB, g_hB);
    cudaGetSymbolAddress((void**)&h16A, g_h16A);
    cudaGetSymbolAddress((void**)&h16B, g_h16B);

    // CSR build + pre (pre moved to 3rd launch so the profiled 4th launch is k_hist)
    k_detect<<<1, 32>>>((const int*)ei);
    k_zero_cnt<<<(N_NODES + 255) / 256, 256>>>();
    k_pre<<<(N_NODES * HID + 255) / 256, 256>>>(x, preW, preb, hA, h16A);
    k_hist<<<(N_EDGES + 255) / 256, 256>>>(ei);
    k_scan1<<<SCAN_NB, SCAN_T>>>();
    k_scan2<<<1, 32>>>();
    k_scan3<<<SCAN_NB, SCAN_T>>>();
    k_scatter<<<(N_EDGES + 255) / 256, 256>>>(ei);

    const int agg_blocks = (N_NODES * 16 + 255) / 256;
    const int xf_blocks  = (N_NODES + 127) / 128;

    // layer 0: A -> B ; layer 1: B -> A ; layer 2 (last, fused post): A -> out
    k_agg<<<agg_blocks, 256>>>(h16A);
    k_xf<0><<<xf_blocks, 256, XF_SMEM0>>>(hA, relW[0], relb[0], rootW[0], postW, postb, hB, h16B);
    k_agg<<<agg_blocks, 256>>>(h16B);
    k_xf<0><<<xf_blocks, 256, XF_SMEM0>>>(hB, relW[1], relb[1], rootW[1], postW, postb, hA, h16A);
    k_agg<<<agg_blocks, 256>>>(h16A);
    k_xf<1><<<xf_blocks, 256, XF_SMEM1>>>(hA, relW[2], relb[2], rootW[2], postW, postb, out, h16B);
}